// round 11
// baseline (speedup 1.0000x reference)
#include <cuda_runtime.h>
#include <cuda_fp16.h>
#include <math.h>
#include <cstdint>

#define LSEQ   1024
#define NBATCH 64
#define NCH    64
#define NSTEP  1056          /* steps per strip: 1024 + 31 + pad */
#define BIGC   1.0e10f
#define LOG2E  1.4426950408889634f
#define LN2F   0.6931471805599453f

/* Strip-step-major scratch (fp16): g_D1h[b][w][s][l] = D[32w+l][s-l]*log2(e).
   138 MB. Slots with s-l outside [0,1023] stay 0 (harmless). */
__device__ __half g_D1h[(size_t)NBATCH * 32 * NSTEP * 32];

__device__ __forceinline__ float ex2(float z) {
    float r; asm("ex2.approx.f32 %0, %1;" : "=f"(r) : "f"(z)); return r;
}
__device__ __forceinline__ float lg2(float z) {
    float r; asm("lg2.approx.f32 %0, %1;" : "=f"(r) : "f"(z)); return r;
}
__device__ __forceinline__ uint32_t f2tf32(float v) {
    uint32_t r; asm("cvt.rna.tf32.f32 %0, %1;" : "=r"(r) : "f"(v)); return r;
}
/* softmin in base-2 domain: -log2(2^-a + 2^-u + 2^-lf), 3 MUFU */
__device__ __forceinline__ float softmin3(float a, float u, float lf) {
    float mn1 = fminf(a, u);
    float mx1 = fmaxf(a, u);
    float m   = fminf(mn1, lf);
    float M   = fmaxf(mx1, lf);
    float med = fmaxf(mn1, fminf(mx1, lf));
    float e   = 1.0f + ex2(m - med) + ex2(m - M);
    return m - lg2(e);
}

/* ------------------------------------------------------------------ */
/* Kernel A: D = (x2 + y2 - 2*x.y^T) * log2(e) via tf32 mma.sync,     */
/* written (fp16) into the strip-step-major layout g_D1h.              */
/* ------------------------------------------------------------------ */
__global__ void __launch_bounds__(256)
compute_D_kernel(const float* __restrict__ x, const float* __restrict__ y) {
    const int b  = blockIdx.y;
    const int ti = blockIdx.x >> 4;
    const int tj = blockIdx.x & 15;
    const int i0 = ti * 64, j0 = tj * 64;

    __shared__ float sbuf[2 * 64 * 68];
    __shared__ float sx2[64], sy2[64];
    float* xs = sbuf;
    float* ys = sbuf + 64 * 68;

    const int tid = threadIdx.x;
    const float4* xb4 = (const float4*)(x + ((size_t)b * LSEQ + i0) * NCH);
    const float4* yb4 = (const float4*)(y + ((size_t)b * LSEQ + j0) * NCH);

#pragma unroll
    for (int k = 0; k < 4; k++) {
        int e = tid + 256 * k;
        int r = e >> 4, c4v = e & 15;
        float4 vx = xb4[r * 16 + c4v];
        float4 vy = yb4[r * 16 + c4v];
        vx.x = __uint_as_float(f2tf32(vx.x)); vx.y = __uint_as_float(f2tf32(vx.y));
        vx.z = __uint_as_float(f2tf32(vx.z)); vx.w = __uint_as_float(f2tf32(vx.w));
        vy.x = __uint_as_float(f2tf32(vy.x)); vy.y = __uint_as_float(f2tf32(vy.y));
        vy.z = __uint_as_float(f2tf32(vy.z)); vy.w = __uint_as_float(f2tf32(vy.w));
        *(float4*)&xs[r * 68 + c4v * 4] = vx;
        *(float4*)&ys[r * 68 + c4v * 4] = vy;
    }
    __syncthreads();

    if (tid < 64) {
        float s = 0.f;
#pragma unroll
        for (int c = 0; c < 64; c++) { float v = xs[tid * 68 + c]; s += v * v; }
        sx2[tid] = s;
    } else if (tid < 128) {
        int r = tid - 64;
        float s = 0.f;
#pragma unroll
        for (int c = 0; c < 64; c++) { float v = ys[r * 68 + c]; s += v * v; }
        sy2[r] = s;
    }
    __syncthreads();

    const int wrp  = tid >> 5, lane = tid & 31;
    const int wr   = wrp & 3, wc = wrp >> 2;
    const int r4   = lane >> 2, c4 = lane & 3;
    const float* As = xs + (wr * 16) * 68;
    const float* Bs = ys + (wc * 32) * 68;

    float cc[4][4];
#pragma unroll
    for (int nt = 0; nt < 4; nt++)
#pragma unroll
        for (int q = 0; q < 4; q++) cc[nt][q] = 0.f;

#pragma unroll
    for (int k0 = 0; k0 < 64; k0 += 8) {
        uint32_t a0 = __float_as_uint(As[(r4)     * 68 + k0 + c4]);
        uint32_t a1 = __float_as_uint(As[(r4 + 8) * 68 + k0 + c4]);
        uint32_t a2 = __float_as_uint(As[(r4)     * 68 + k0 + c4 + 4]);
        uint32_t a3 = __float_as_uint(As[(r4 + 8) * 68 + k0 + c4 + 4]);
#pragma unroll
        for (int nt = 0; nt < 4; nt++) {
            uint32_t b0 = __float_as_uint(Bs[(nt * 8 + r4) * 68 + k0 + c4]);
            uint32_t b1 = __float_as_uint(Bs[(nt * 8 + r4) * 68 + k0 + c4 + 4]);
            asm volatile(
                "mma.sync.aligned.m16n8k8.row.col.f32.tf32.tf32.f32 "
                "{%0,%1,%2,%3}, {%4,%5,%6,%7}, {%8,%9}, {%0,%1,%2,%3};"
                : "+f"(cc[nt][0]), "+f"(cc[nt][1]), "+f"(cc[nt][2]), "+f"(cc[nt][3])
                : "r"(a0), "r"(a1), "r"(a2), "r"(a3), "r"(b0), "r"(b1));
        }
    }
    __syncthreads();

    float* Dt = sbuf;                 /* Dt_T[jl][il], stride 67 */
    const int row0 = wr * 16 + r4;
#pragma unroll
    for (int nt = 0; nt < 4; nt++) {
        int colb = wc * 32 + nt * 8 + 2 * c4;
        Dt[colb * 67 + row0]           = (sx2[row0]     + sy2[colb]     - 2.0f * cc[nt][0]) * LOG2E;
        Dt[(colb + 1) * 67 + row0]     = (sx2[row0]     + sy2[colb + 1] - 2.0f * cc[nt][1]) * LOG2E;
        Dt[colb * 67 + row0 + 8]       = (sx2[row0 + 8] + sy2[colb]     - 2.0f * cc[nt][2]) * LOG2E;
        Dt[(colb + 1) * 67 + row0 + 8] = (sx2[row0 + 8] + sy2[colb + 1] - 2.0f * cc[nt][3]) * LOG2E;
    }
    __syncthreads();

    /* strip w = 2*ti + h owns rows 32h..32h+31 of this tile; lane l   */
    /* writes D[i0+32h+l][j0+so-l] (fp16) at g_D1h[b][w][j0+so][l].     */
    const int h  = wrp & 1;
    const int w4 = wrp >> 1;
    const size_t gbase = ((size_t)(b * 32 + ti * 2 + h) * NSTEP + j0) * 32;
    for (int so = w4; so < 95; so += 4) {
        int jl = so - lane;
        if (jl >= 0 && jl < 64) {
            g_D1h[gbase + (size_t)so * 32 + lane] =
                __float2half_rn(Dt[jl * 67 + 32 * h + lane]);
        }
    }
}

/* ------------------------------------------------------------------ */
/* Kernel B: 32 warps x 1 row/lane, barrier-paced, CH=8, KOFF=11.      */
/* Lag 88 steps: ~11 concurrent active warps -> issue/MUFU contention  */
/* drops to the serial-chain floor while path grows only 33%.          */
/* ------------------------------------------------------------------ */
#define CH      8
#define NCHUNK  132                     /* 132*8 = 1056 steps */
#define KOFF    11
#define NROUNDS (KOFF * 31 + NCHUNK)    /* 473 */

__global__ void __launch_bounds__(1024)
sdtw_pipeline_kernel(float* __restrict__ out) {
    const int b   = blockIdx.x;
    const int tid = threadIdx.x;
    const int w   = tid >> 5;
    const int l   = tid & 31;

    __shared__ float rb[31][128];       /* boundary rings: rb[w] fed by warp w lane 31 */

    for (int e = tid; e < 31 * 128; e += 1024) ((float*)rb)[e] = BIGC;
    __syncthreads();

    float v1     = BIGC;                            /* left operand  */
    float u_prev = (w == 0 && l == 0) ? 0.0f : BIGC;/* diag operand  */
    float result = 0.0f;

    const __half* dp  = g_D1h + ((size_t)(b * 32 + w) * NSTEP) * 32 + l;
    float*        rbw = (w < 31) ? rb[w] : rb[0];
    const float*  rbr = (w > 0) ? rb[w - 1] : rb[0];

    float dv[CH];
    if (w == 0) {
#pragma unroll
        for (int k = 0; k < CH; k++) dv[k] = __half2float(dp[(size_t)k * 32]);
    }

    for (int r = 0; r < NROUNDS; r++) {
        const int c  = r - KOFF * w;
        const int cn = c + 1;

        /* prefetch next chunk (consumed next round) */
        float dn[CH];
        const bool pf = (cn >= 0) && (cn < NCHUNK);
        if (pf) {
            const __half* dpn = dp + (size_t)(cn * CH) * 32;
#pragma unroll
            for (int k = 0; k < CH; k++) dn[k] = __half2float(dpn[(size_t)k * 32]);
        }

        if (c >= 0 && c < NCHUNK) {
            const int sc = c * CH;
#pragma unroll
            for (int k = 0; k < CH; k++) {
                const int s = sc + k;
                float rv = rbr[(s + 1) & 127];              /* broadcast LDS */
                float u  = __shfl_up_sync(0xffffffffu, v1, 1);
                if (l == 0) u = (w == 0) ? BIGC : rv;
                float nv = dv[k] + softmin3(u_prev, u, v1);
                if (l == 31) {
                    if (w < 31) rbw[(s - 30) & 127] = nv;
                    else if (s == 1054) result = nv;        /* R[1024][1024] */
                }
                v1     = nv;
                u_prev = u;
            }
        }

        if (pf) {
#pragma unroll
            for (int k = 0; k < CH; k++) dv[k] = dn[k];
        }
        __syncthreads();
    }

    if (w == 31 && l == 31) out[b] = result * LN2F;
}

/* ------------------------------------------------------------------ */
extern "C" void kernel_launch(void* const* d_in, const int* in_sizes, int n_in,
                              void* d_out, int out_size) {
    (void)in_sizes; (void)n_in; (void)out_size;
    const float* x = (const float*)d_in[0];
    const float* y = (const float*)d_in[1];
    float* out = (float*)d_out;

    dim3 gridA(256, NBATCH);
    compute_D_kernel<<<gridA, 256>>>(x, y);
    sdtw_pipeline_kernel<<<NBATCH, 1024>>>(out);
}

// round 12
// speedup vs baseline: 2.2427x; 2.2427x over previous
#include <cuda_runtime.h>
#include <math.h>
#include <cstdint>

#define LSEQ   1024
#define NBATCH 64
#define NCH    64
#define NSTEP  1056          /* steps per strip: 1024 + 31 + pad */
#define BIGC   1.0e10f
#define LOG2E  1.4426950408889634f
#define LN2F   0.6931471805599453f

/* Strip-step-major scratch: g_D1[b][w][s][l] = D[32w+l][s-l] * log2(e).
   277 MB. Slots with s-l outside [0,1023] are never written and stay 0. */
__device__ float g_D1[(size_t)NBATCH * 32 * NSTEP * 32];

__device__ __forceinline__ float ex2(float z) {
    float r; asm("ex2.approx.f32 %0, %1;" : "=f"(r) : "f"(z)); return r;
}
__device__ __forceinline__ float lg2(float z) {
    float r; asm("lg2.approx.f32 %0, %1;" : "=f"(r) : "f"(z)); return r;
}
__device__ __forceinline__ uint32_t f2tf32(float v) {
    uint32_t r; asm("cvt.rna.tf32.f32 %0, %1;" : "=r"(r) : "f"(v)); return r;
}
/* softmin in base-2 domain: -log2(2^-a + 2^-u + 2^-lf), 3 MUFU */
__device__ __forceinline__ float softmin3(float a, float u, float lf) {
    float mn1 = fminf(a, u);
    float mx1 = fmaxf(a, u);
    float m   = fminf(mn1, lf);
    float M   = fmaxf(mx1, lf);
    float med = fmaxf(mn1, fminf(mx1, lf));
    float e   = 1.0f + ex2(m - med) + ex2(m - M);
    return m - lg2(e);
}

/* ------------------------------------------------------------------ */
/* Kernel A: D = (x2 + y2 - 2*x.y^T) * log2(e) via tf32 mma.sync,     */
/* written into the strip-step-major layout g_D1. Norms computed by    */
/* all 256 threads (4 threads/row + shfl_xor reduce).                  */
/* ------------------------------------------------------------------ */
__global__ void __launch_bounds__(256)
compute_D_kernel(const float* __restrict__ x, const float* __restrict__ y) {
    const int b  = blockIdx.y;
    const int ti = blockIdx.x >> 4;
    const int tj = blockIdx.x & 15;
    const int i0 = ti * 64, j0 = tj * 64;

    __shared__ float sbuf[2 * 64 * 68];
    __shared__ float sx2[64], sy2[64];
    float* xs = sbuf;
    float* ys = sbuf + 64 * 68;

    const int tid = threadIdx.x;
    const float4* xb4 = (const float4*)(x + ((size_t)b * LSEQ + i0) * NCH);
    const float4* yb4 = (const float4*)(y + ((size_t)b * LSEQ + j0) * NCH);

#pragma unroll
    for (int k = 0; k < 4; k++) {
        int e = tid + 256 * k;
        int r = e >> 4, c4v = e & 15;
        float4 vx = xb4[r * 16 + c4v];
        float4 vy = yb4[r * 16 + c4v];
        vx.x = __uint_as_float(f2tf32(vx.x)); vx.y = __uint_as_float(f2tf32(vx.y));
        vx.z = __uint_as_float(f2tf32(vx.z)); vx.w = __uint_as_float(f2tf32(vx.w));
        vy.x = __uint_as_float(f2tf32(vy.x)); vy.y = __uint_as_float(f2tf32(vy.y));
        vy.z = __uint_as_float(f2tf32(vy.z)); vy.w = __uint_as_float(f2tf32(vy.w));
        *(float4*)&xs[r * 68 + c4v * 4] = vx;
        *(float4*)&ys[r * 68 + c4v * 4] = vy;
    }
    __syncthreads();

    /* norms: 4 threads per row, 16 elems each, butterfly-reduce */
    {
        const int row  = tid >> 2;        /* 0..63 */
        const int part = tid & 3;         /* 0..3  */
        float sx = 0.f, sy = 0.f;
        const float* xr = &xs[row * 68 + part * 16];
        const float* yr = &ys[row * 68 + part * 16];
#pragma unroll
        for (int c = 0; c < 16; c += 4) {
            float4 vx = *(const float4*)&xr[c];
            float4 vy = *(const float4*)&yr[c];
            sx += vx.x * vx.x + vx.y * vx.y + vx.z * vx.z + vx.w * vx.w;
            sy += vy.x * vy.x + vy.y * vy.y + vy.z * vy.z + vy.w * vy.w;
        }
        sx += __shfl_xor_sync(0xffffffffu, sx, 1);
        sx += __shfl_xor_sync(0xffffffffu, sx, 2);
        sy += __shfl_xor_sync(0xffffffffu, sy, 1);
        sy += __shfl_xor_sync(0xffffffffu, sy, 2);
        if (part == 0) { sx2[row] = sx; sy2[row] = sy; }
    }
    __syncthreads();

    const int wrp  = tid >> 5, lane = tid & 31;
    const int wr   = wrp & 3, wc = wrp >> 2;
    const int r4   = lane >> 2, c4 = lane & 3;
    const float* As = xs + (wr * 16) * 68;
    const float* Bs = ys + (wc * 32) * 68;

    float cc[4][4];
#pragma unroll
    for (int nt = 0; nt < 4; nt++)
#pragma unroll
        for (int q = 0; q < 4; q++) cc[nt][q] = 0.f;

#pragma unroll
    for (int k0 = 0; k0 < 64; k0 += 8) {
        uint32_t a0 = __float_as_uint(As[(r4)     * 68 + k0 + c4]);
        uint32_t a1 = __float_as_uint(As[(r4 + 8) * 68 + k0 + c4]);
        uint32_t a2 = __float_as_uint(As[(r4)     * 68 + k0 + c4 + 4]);
        uint32_t a3 = __float_as_uint(As[(r4 + 8) * 68 + k0 + c4 + 4]);
#pragma unroll
        for (int nt = 0; nt < 4; nt++) {
            uint32_t b0 = __float_as_uint(Bs[(nt * 8 + r4) * 68 + k0 + c4]);
            uint32_t b1 = __float_as_uint(Bs[(nt * 8 + r4) * 68 + k0 + c4 + 4]);
            asm volatile(
                "mma.sync.aligned.m16n8k8.row.col.f32.tf32.tf32.f32 "
                "{%0,%1,%2,%3}, {%4,%5,%6,%7}, {%8,%9}, {%0,%1,%2,%3};"
                : "+f"(cc[nt][0]), "+f"(cc[nt][1]), "+f"(cc[nt][2]), "+f"(cc[nt][3])
                : "r"(a0), "r"(a1), "r"(a2), "r"(a3), "r"(b0), "r"(b1));
        }
    }
    __syncthreads();

    float* Dt = sbuf;                 /* Dt_T[jl][il], stride 67 */
    const int row0 = wr * 16 + r4;
#pragma unroll
    for (int nt = 0; nt < 4; nt++) {
        int colb = wc * 32 + nt * 8 + 2 * c4;
        Dt[colb * 67 + row0]           = (sx2[row0]     + sy2[colb]     - 2.0f * cc[nt][0]) * LOG2E;
        Dt[(colb + 1) * 67 + row0]     = (sx2[row0]     + sy2[colb + 1] - 2.0f * cc[nt][1]) * LOG2E;
        Dt[colb * 67 + row0 + 8]       = (sx2[row0 + 8] + sy2[colb]     - 2.0f * cc[nt][2]) * LOG2E;
        Dt[(colb + 1) * 67 + row0 + 8] = (sx2[row0 + 8] + sy2[colb + 1] - 2.0f * cc[nt][3]) * LOG2E;
    }
    __syncthreads();

    /* strip w = 2*ti + h owns rows 32h..32h+31 of this tile; lane l   */
    /* writes D[i0+32h+l][j0+so-l] at g_D1[b][w][j0+so][l].             */
    const int h  = wrp & 1;
    const int w4 = wrp >> 1;
    const size_t gbase = ((size_t)(b * 32 + ti * 2 + h) * NSTEP + j0) * 32;
    for (int so = w4; so < 95; so += 4) {
        int jl = so - lane;
        if (jl >= 0 && jl < 64) {
            g_D1[gbase + (size_t)so * 32 + lane] = Dt[jl * 67 + 32 * h + lane];
        }
    }
}

/* ------------------------------------------------------------------ */
/* Kernel B: R8 exact — 32 warps x 1 row/lane, barrier-paced,          */
/* CH=8 / KOFF=5 (lag 40), double-buffered D prefetch, unguarded body. */
/* ------------------------------------------------------------------ */
#define CH      8
#define NCHUNK  132                     /* 132*8 = 1056 >= 1055 steps */
#define KOFF    5
#define NROUNDS (KOFF * 31 + NCHUNK)    /* 287 */

__global__ void __launch_bounds__(1024)
sdtw_pipeline_kernel(float* __restrict__ out) {
    const int b   = blockIdx.x;
    const int tid = threadIdx.x;
    const int w   = tid >> 5;
    const int l   = tid & 31;

    __shared__ float rb[31][128];       /* boundary rings: rb[w] fed by warp w lane 31 */

    for (int e = tid; e < 31 * 128; e += 1024) ((float*)rb)[e] = BIGC;
    __syncthreads();

    float v1     = BIGC;                            /* left operand  */
    float u_prev = (w == 0 && l == 0) ? 0.0f : BIGC;/* diag operand  */
    float result = 0.0f;

    const float* dp  = g_D1 + ((size_t)(b * 32 + w) * NSTEP) * 32 + l;
    float*       rbw = (w < 31) ? rb[w] : rb[0];
    const float* rbr = (w > 0) ? rb[w - 1] : rb[0];

    float dv[CH];
    if (w == 0) {                        /* warp 0 preloads its chunk 0 */
#pragma unroll
        for (int k = 0; k < CH; k++) dv[k] = dp[(size_t)k * 32];
    }

    for (int r = 0; r < NROUNDS; r++) {
        const int c  = r - KOFF * w;
        const int cn = c + 1;

        /* prefetch next chunk (consumed next round) */
        float dn[CH];
        const bool pf = (cn >= 0) && (cn < NCHUNK);
        if (pf) {
            const float* dpn = dp + (size_t)(cn * CH) * 32;
#pragma unroll
            for (int k = 0; k < CH; k++) dn[k] = dpn[(size_t)k * 32];
        }

        if (c >= 0 && c < NCHUNK) {
            const int sc = c * CH;
#pragma unroll
            for (int k = 0; k < CH; k++) {
                const int s = sc + k;
                float rv = rbr[(s + 1) & 127];              /* broadcast LDS */
                float u  = __shfl_up_sync(0xffffffffu, v1, 1);
                if (l == 0) u = (w == 0) ? BIGC : rv;
                float nv = dv[k] + softmin3(u_prev, u, v1);
                if (l == 31) {
                    if (w < 31) rbw[(s - 30) & 127] = nv;
                    else if (s == 1054) result = nv;        /* R[1024][1024] */
                }
                v1     = nv;
                u_prev = u;
            }
        }

        if (pf) {
#pragma unroll
            for (int k = 0; k < CH; k++) dv[k] = dn[k];
        }
        __syncthreads();
    }

    if (w == 31 && l == 31) out[b] = result * LN2F;
}

/* ------------------------------------------------------------------ */
extern "C" void kernel_launch(void* const* d_in, const int* in_sizes, int n_in,
                              void* d_out, int out_size) {
    (void)in_sizes; (void)n_in; (void)out_size;
    const float* x = (const float*)d_in[0];
    const float* y = (const float*)d_in[1];
    float* out = (float*)d_out;

    dim3 gridA(256, NBATCH);
    compute_D_kernel<<<gridA, 256>>>(x, y);
    sdtw_pipeline_kernel<<<NBATCH, 1024>>>(out);
}